// round 5
// baseline (speedup 1.0000x reference)
#include <cuda_runtime.h>
#include <cuda_bf16.h>
#include <math.h>

// Problem dims (fixed)
#define BB    64      // batch
#define LL    64      // encoder seq len
#define VV    32000   // vocab
#define TT    32      // decoder steps
#define DEMB  128
#define DENC  256
#define DDEC  512
#define NHH   8
#define HDD   64
#define NPROJ 500     // 32000/64 proj tiles

struct Scratch {
    float x[LL*BB*DEMB];          // [L,B,128] token embeddings
    float Xpre[LL*BB*2048];       // x @ [WihT_f | WihT_b]
    float WihT[DEMB*2048];        // [128, 2048]
    float WhhT[DENC*2048];        // [256, 2048]
    float WdecT[640*2048];        // [640, 2048] concat(WihT_dec, WhhT_dec)
    float WqT[512*512];
    float WkvT[512*1024];
    float WoutT[512*512];
    float transferT[512*512];
    float projT[512*VV];          // [512, 32000]
    float mem[LL*BB*512];         // encoder memory [L,B,512]
    float kv[LL*BB*1024];         // k (0..511), v (512..1023)
    float hf[2][BB*DENC];
    float hb[2][BB*DENC];
    float cf[BB*DENC];
    float cb[BB*DENC];
    float z[BB*640];              // [xe(128) | h(512)] decoder input
    float c[BB*512];
    float hstar[BB*512];
    float q[BB*512];
    float ctx[BB*512];
    float y[BB*512];
    float gates[BB*2048];
    float pmax[BB*512];
    int   pidx[BB*512];
};

__device__ Scratch S;

__device__ __forceinline__ float sigf(float x){ return 1.0f/(1.0f + expf(-x)); }

// ---------------------------------------------------------------------------
// init: zero encoder states, seed decoder xe with start_emb
// ---------------------------------------------------------------------------
__global__ void k_init(const float* __restrict__ start_emb){
    int i = blockIdx.x*blockDim.x + threadIdx.x;
    int stride = gridDim.x*blockDim.x;
    for (int idx=i; idx < BB*DENC; idx += stride){
        S.hf[0][idx]=0.f; S.hb[0][idx]=0.f; S.cf[idx]=0.f; S.cb[idx]=0.f;
    }
    for (int idx=i; idx < BB*DEMB; idx += stride)
        S.z[(idx>>7)*640 + (idx&127)] = start_emb[idx&127];
}

// ---------------------------------------------------------------------------
// embed: x[l,b,:] = tok_emb[nx[b,l]]
// ---------------------------------------------------------------------------
__global__ void k_embed(const int* __restrict__ nx, const float* __restrict__ tok_emb){
    int n = blockIdx.x;                 // n = l*B + b
    int e = threadIdx.x;                // 128 threads
    int l = n >> 6, b = n & 63;
    S.x[(size_t)n*DEMB + e] = tok_emb[(size_t)nx[b*LL + l]*DEMB + e];
}

// ---------------------------------------------------------------------------
// generic 32x32 tiled transpose: dst[k*dld + j] = src[(row0+j)*ncols + k]
// ---------------------------------------------------------------------------
__global__ void k_transpose(const float* __restrict__ src, int row0, int nrows,
                            int ncols, float* __restrict__ dst, int dld){
    __shared__ float tile[32][33];
    int j0 = blockIdx.x*32, k0 = blockIdx.y*32;
    int x = threadIdx.x;
    #pragma unroll
    for (int i=0;i<32;i+=8){
        int j = j0 + threadIdx.y + i;
        int k = k0 + x;
        tile[threadIdx.y+i][x] = (j<nrows && k<ncols) ? src[(size_t)(row0+j)*ncols + k] : 0.f;
    }
    __syncthreads();
    #pragma unroll
    for (int i=0;i<32;i+=8){
        int k = k0 + threadIdx.y + i;
        int j = j0 + x;
        if (k<ncols && j<nrows) dst[(size_t)k*dld + j] = tile[x][threadIdx.y+i];
    }
}

// ---------------------------------------------------------------------------
// generic fp32 SGEMM: C[M,N] = alpha*(A@B + bias) + resid
// BM=BN=64, BK=16, 256 threads, 4x4 microtile.
// Optional per-block row-argmax epilogue (requires gridDim.y==1, M==64).
// ---------------------------------------------------------------------------
__global__ void __launch_bounds__(256) k_sgemm(
    const float* __restrict__ A, int lda,
    const float* __restrict__ B, int ldb,
    const float* __restrict__ bias,
    const float* __restrict__ resid, int ldr,
    float* __restrict__ C, int ldc,
    int M, int N, int K, float alpha,
    float* __restrict__ pmax, int* __restrict__ pidx)
{
    __shared__ float As[16][68];
    __shared__ float Bs[16][64];
    int tid = threadIdx.x;
    int tx = tid & 15, ty = tid >> 4;
    int m0 = blockIdx.y*64, n0 = blockIdx.x*64;
    float acc[4][4] = {};

    for (int k0 = 0; k0 < K; k0 += 16){
        #pragma unroll
        for (int u=0;u<4;u++){
            int idx = tid + u*256;
            int i = idx >> 4, j = idx & 15;
            As[j][i] = A[(size_t)(m0+i)*lda + k0 + j];
        }
        #pragma unroll
        for (int u=0;u<4;u++){
            int idx = tid + u*256;
            int i = idx & 63, j = idx >> 6;
            Bs[j][i] = B[(size_t)(k0+j)*ldb + n0 + i];
        }
        __syncthreads();
        #pragma unroll
        for (int k=0;k<16;k++){
            float4 a4 = *(const float4*)&As[k][ty*4];
            float4 b4 = *(const float4*)&Bs[k][tx*4];
            float av[4] = {a4.x,a4.y,a4.z,a4.w};
            float bv[4] = {b4.x,b4.y,b4.z,b4.w};
            #pragma unroll
            for (int r=0;r<4;r++)
                #pragma unroll
                for (int c=0;c<4;c++)
                    acc[r][c] += av[r]*bv[c];
        }
        __syncthreads();
    }

    float rowmax[4]; int rowidx[4];
    #pragma unroll
    for (int r=0;r<4;r++){
        int m = m0 + ty*4 + r;
        float bm = -1e30f; int bi = 0;
        #pragma unroll
        for (int c=0;c<4;c++){
            int n = n0 + tx*4 + c;
            float v = acc[r][c];
            if (bias)  v += bias[n];
            v *= alpha;
            if (resid) v += resid[(size_t)m*ldr + n];
            C[(size_t)m*ldc + n] = v;
            if (v > bm){ bm = v; bi = n; }
        }
        rowmax[r] = bm; rowidx[r] = bi;
    }

    if (pmax){
        __shared__ float smx[64][17];
        __shared__ int   smi[64][17];
        #pragma unroll
        for (int r=0;r<4;r++){ smx[ty*4+r][tx] = rowmax[r]; smi[ty*4+r][tx] = rowidx[r]; }
        __syncthreads();
        if (tid < 64){
            float bm = -1e30f; int bi = 0;
            #pragma unroll
            for (int c=0;c<16;c++){
                float v = smx[tid][c];
                if (v > bm){ bm = v; bi = smi[tid][c]; }
            }
            pmax[tid*512 + blockIdx.x] = bm;
            pidx[tid*512 + blockIdx.x] = bi;
        }
    }
}

// ---------------------------------------------------------------------------
// encoder step (both directions): gates = Xpre + h@WhhT + b, LSTM cell.
// Ping-pong h buffers on t parity (avoids intra-launch read/write races).
// block: 16 batch rows x 32 hidden cols, 256 threads (each thread: 2 rows)
// grid: (8 hidgroups, 4 rowgroups, 2 dirs)
// ---------------------------------------------------------------------------
__global__ void __launch_bounds__(256) k_encstep(int t,
        const float* __restrict__ bias_f, const float* __restrict__ bias_b){
    __shared__ float sh[16][256];
    int tid = threadIdx.x;
    int tx = tid & 31, ty = tid >> 5;        // ty 0..7
    int dir = blockIdx.z;
    int b0 = blockIdx.y * 16;
    int jh = blockIdx.x * 32 + tx;

    const float* hrd = dir ? S.hb[t & 1]     : S.hf[t & 1];
    float*       hwr = dir ? S.hb[(t+1)&1]   : S.hf[(t+1)&1];
    float*       cbuf = dir ? S.cb : S.cf;

    for (int idx = tid; idx < 16*256; idx += 256)
        sh[idx >> 8][idx & 255] = hrd[(b0 + (idx >> 8))*256 + (idx & 255)];
    __syncthreads();

    const float* W = S.WhhT + dir*1024 + jh;
    float a00=0,a01=0,a02=0,a03=0,a10=0,a11=0,a12=0,a13=0;
    #pragma unroll 4
    for (int k=0;k<256;k++){
        const float* wr = W + (size_t)k*2048;
        float w0 = wr[0], w1 = wr[256], w2 = wr[512], w3 = wr[768];
        float h0v = sh[ty][k], h1v = sh[ty+8][k];
        a00 += h0v*w0; a01 += h0v*w1; a02 += h0v*w2; a03 += h0v*w3;
        a10 += h1v*w0; a11 += h1v*w1; a12 += h1v*w2; a13 += h1v*w3;
    }

    int xrow = dir ? (LL - 1 - t) : t;
    const float* bias = dir ? bias_b : bias_f;
    float bi_ = bias[jh], bf_ = bias[256+jh], bg_ = bias[512+jh], bo_ = bias[768+jh];

    #pragma unroll
    for (int rr=0;rr<2;rr++){
        int b = b0 + ty + rr*8;
        const float* xp = S.Xpre + ((size_t)(xrow*BB + b))*2048 + dir*1024;
        float gi = (rr ? a10 : a00) + xp[jh]       + bi_;
        float gf = (rr ? a11 : a01) + xp[256+jh]   + bf_;
        float gg = (rr ? a12 : a02) + xp[512+jh]   + bg_;
        float go = (rr ? a13 : a03) + xp[768+jh]   + bo_;
        float cprev = cbuf[b*256 + jh];
        float cc = sigf(gf)*cprev + sigf(gi)*tanhf(gg);
        float hh = sigf(go)*tanhf(cc);
        cbuf[b*256 + jh] = cc;
        hwr[b*256 + jh]  = hh;
        S.mem[((size_t)xrow*BB + b)*512 + dir*256 + jh] = hh;
    }
}

// ---------------------------------------------------------------------------
// h0 = tanh(concat(hf,hb) @ transferT) -> z[:,128:640];  c0 = style_emb[label]
// grid (16, 8), 256 threads (8 rows x 32 cols)
// ---------------------------------------------------------------------------
__global__ void __launch_bounds__(256) k_h0(const int* __restrict__ label,
                                            const float* __restrict__ style_emb){
    __shared__ float sh[8][512];
    int tid = threadIdx.x, tx = tid & 31, ty = tid >> 5;
    int b0 = blockIdx.y*8;
    int j  = blockIdx.x*32 + tx;
    for (int idx=tid; idx<8*512; idx+=256){
        int r = idx >> 9, c = idx & 511;
        sh[r][c] = (c < 256) ? S.hf[0][(b0+r)*256 + c]
                             : S.hb[0][(b0+r)*256 + c - 256];
    }
    __syncthreads();
    float acc = 0.f;
    #pragma unroll 4
    for (int k=0;k<512;k++) acc += sh[ty][k]*S.transferT[(size_t)k*512 + j];
    int b = b0 + ty;
    S.z[b*640 + 128 + j] = tanhf(acc);
    S.c[b*512 + j] = style_emb[(size_t)label[b]*512 + j];
}

// ---------------------------------------------------------------------------
// decoder LSTM cell (post-GEMM): gate order i,f,g,o (chunks of 512)
// ---------------------------------------------------------------------------
__global__ void k_deccell(){
    int b = blockIdx.x, j = threadIdx.x;   // 512 threads
    const float* g = S.gates + b*2048;
    float gi = g[j], gf = g[512+j], gg = g[1024+j], go = g[1536+j];
    float c = sigf(gf)*S.c[b*512+j] + sigf(gi)*tanhf(gg);
    S.c[b*512+j] = c;
    S.hstar[b*512+j] = sigf(go)*tanhf(c);
}

// ---------------------------------------------------------------------------
// single-query multi-head attention: grid (NH, B), 64 threads
// ---------------------------------------------------------------------------
__global__ void k_attn(){
    int h = blockIdx.x, b = blockIdx.y;
    int l = threadIdx.x;   // 64
    __shared__ float sq[64], sc[64], red[64];
    sq[l] = S.q[b*512 + h*64 + l];
    __syncthreads();
    const float* kp = S.kv + ((size_t)l*BB + b)*1024 + h*64;
    float s = 0.f;
    #pragma unroll
    for (int d=0;d<64;d++) s += sq[d]*kp[d];
    sc[l] = s; red[l] = s;
    __syncthreads();
    for (int off=32; off; off>>=1){
        if (l < off) red[l] = fmaxf(red[l], red[l+off]);
        __syncthreads();
    }
    float m = red[0];
    __syncthreads();
    float e = expf(s - m);
    sc[l] = e; red[l] = e;
    __syncthreads();
    for (int off=32; off; off>>=1){
        if (l < off) red[l] += red[l+off];
        __syncthreads();
    }
    float inv = 1.f/red[0];
    // ctx: thread index now = head dim d
    int d = l;
    float acc = 0.f;
    #pragma unroll 4
    for (int l2=0;l2<64;l2++)
        acc += sc[l2] * S.kv[((size_t)l2*BB + b)*1024 + 512 + h*64 + d];
    S.ctx[b*512 + h*64 + d] = acc * inv;
}

// ---------------------------------------------------------------------------
// LayerNorm over 512: reads S.y, writes z[:,128:640]
// ---------------------------------------------------------------------------
__global__ void k_ln(const float* __restrict__ lng, const float* __restrict__ lnb){
    int b = blockIdx.x, j = threadIdx.x;   // 512 threads
    float y = S.y[b*512 + j];
    float v1 = y, v2 = y*y;
    #pragma unroll
    for (int off=16; off; off>>=1){
        v1 += __shfl_down_sync(0xffffffffu, v1, off);
        v2 += __shfl_down_sync(0xffffffffu, v2, off);
    }
    __shared__ float s1[16], s2[16];
    __shared__ float mb[2];
    int wid = j >> 5, lane = j & 31;
    if (!lane){ s1[wid] = v1; s2[wid] = v2; }
    __syncthreads();
    if (j == 0){
        float a=0.f, cq=0.f;
        #pragma unroll
        for (int i=0;i<16;i++){ a += s1[i]; cq += s2[i]; }
        float mean = a*(1.f/512.f);
        float var  = cq*(1.f/512.f) - mean*mean;
        mb[0] = mean; mb[1] = rsqrtf(var + 1e-5f);
    }
    __syncthreads();
    S.z[b*640 + 128 + j] = (y - mb[0])*mb[1]*lng[j] + lnb[j];
}

// ---------------------------------------------------------------------------
// argmax reduce over NPROJ partials + embedding feedback -> z[:,0:128]
// grid (64), 128 threads
// ---------------------------------------------------------------------------
__global__ void k_feedback(const float* __restrict__ tok_emb){
    int b = blockIdx.x, t = threadIdx.x;   // 128
    float best = -1e30f; int bi = 0x7fffffff;
    for (int i=t; i<NPROJ; i+=128){
        float v = S.pmax[b*512 + i]; int idx = S.pidx[b*512 + i];
        if (v > best || (v == best && idx < bi)){ best = v; bi = idx; }
    }
    __shared__ float sv[128]; __shared__ int si[128];
    sv[t] = best; si[t] = bi;
    __syncthreads();
    for (int off=64; off; off>>=1){
        if (t < off){
            if (sv[t+off] > sv[t] || (sv[t+off] == sv[t] && si[t+off] < si[t])){
                sv[t] = sv[t+off]; si[t] = si[t+off];
            }
        }
        __syncthreads();
    }
    int tok = si[0];
    S.z[b*640 + t] = tok_emb[(size_t)tok*DEMB + t];
}

// ---------------------------------------------------------------------------
// host launch
// ---------------------------------------------------------------------------
extern "C" void kernel_launch(void* const* d_in, const int* in_sizes, int n_in,
                              void* d_out, int out_size){
    const int*   nx         = (const int*)  d_in[0];
    const int*   label      = (const int*)  d_in[1];
    const float* start_emb  = (const float*)d_in[2];
    const float* tok_emb    = (const float*)d_in[3];
    const float* style_emb  = (const float*)d_in[4];
    const float* enc_Wih_f  = (const float*)d_in[5];
    const float* enc_Whh_f  = (const float*)d_in[6];
    const float* enc_b_f    = (const float*)d_in[7];
    const float* enc_Wih_b  = (const float*)d_in[8];
    const float* enc_Whh_b  = (const float*)d_in[9];
    const float* enc_b_b    = (const float*)d_in[10];
    const float* transfer_W = (const float*)d_in[11];
    const float* dec_Wih    = (const float*)d_in[12];
    const float* dec_Whh    = (const float*)d_in[13];
    const float* dec_b      = (const float*)d_in[14];
    const float* attn_in_w  = (const float*)d_in[15];
    const float* attn_in_b  = (const float*)d_in[16];
    const float* attn_out_w = (const float*)d_in[17];
    const float* attn_out_b = (const float*)d_in[18];
    const float* proj_W     = (const float*)d_in[19];
    const float* proj_b     = (const float*)d_in[20];
    const float* ln_g       = (const float*)d_in[21];
    const float* ln_b       = (const float*)d_in[22];
    float* out = (float*)d_out;

    Scratch* sp;
    cudaGetSymbolAddress((void**)&sp, S);

    dim3 tb(32, 8);

    // ---- setup ----
    k_init<<<64, 256>>>(start_emb);
    k_embed<<<LL*BB, 128>>>(nx, tok_emb);

    // weight transposes
    k_transpose<<<dim3(32,  4),  tb>>>(enc_Wih_f, 0, 1024, 128, sp->WihT,              2048);
    k_transpose<<<dim3(32,  4),  tb>>>(enc_Wih_b, 0, 1024, 128, sp->WihT + 1024,       2048);
    k_transpose<<<dim3(32,  8),  tb>>>(enc_Whh_f, 0, 1024, 256, sp->WhhT,              2048);
    k_transpose<<<dim3(32,  8),  tb>>>(enc_Whh_b, 0, 1024, 256, sp->WhhT + 1024,       2048);
    k_transpose<<<dim3(64,  4),  tb>>>(dec_Wih,   0, 2048, 128, sp->WdecT,             2048);
    k_transpose<<<dim3(64, 16),  tb>>>(dec_Whh,   0, 2048, 512, sp->WdecT + 128*2048,  2048);
    k_transpose<<<dim3(16, 16),  tb>>>(attn_in_w,    0, 512, 512, sp->WqT,              512);
    k_transpose<<<dim3(16, 16),  tb>>>(attn_in_w,  512, 512, 512, sp->WkvT,            1024);
    k_transpose<<<dim3(16, 16),  tb>>>(attn_in_w, 1024, 512, 512, sp->WkvT + 512,      1024);
    k_transpose<<<dim3(16, 16),  tb>>>(attn_out_w,   0, 512, 512, sp->WoutT,            512);
    k_transpose<<<dim3(16, 16),  tb>>>(transfer_W,   0, 512, 512, sp->transferT,        512);
    k_transpose<<<dim3(1000,16), tb>>>(proj_W,       0, VV,  512, sp->projT,            VV);

    // Xpre = x @ [WihT_f | WihT_b]   (M=4096, N=2048, K=128)
    k_sgemm<<<dim3(32, 64), 256>>>(sp->x, 128, sp->WihT, 2048,
                                   nullptr, nullptr, 0,
                                   sp->Xpre, 2048, 4096, 2048, 128, 1.f,
                                   nullptr, nullptr);

    // ---- encoder recurrence (both dirs per launch) ----
    for (int t=0; t<LL; t++)
        k_encstep<<<dim3(8, 4, 2), 256>>>(t, enc_b_f, enc_b_b);

    // h0 / c0
    k_h0<<<dim3(16, 8), 256>>>(label, style_emb);

    // k,v = memory @ WkvT + [bk|bv]   (M=4096, N=1024, K=512)
    k_sgemm<<<dim3(16, 64), 256>>>(sp->mem, 512, sp->WkvT, 1024,
                                   attn_in_b + 512, nullptr, 0,
                                   sp->kv, 1024, 4096, 1024, 512, 1.f,
                                   nullptr, nullptr);

    // ---- decoder ----
    for (int t=0; t<TT; t++){
        // gates = z @ WdecT + dec_b   (M=64, N=2048, K=640)
        k_sgemm<<<dim3(32, 1), 256>>>(sp->z, 640, sp->WdecT, 2048,
                                      dec_b, nullptr, 0,
                                      sp->gates, 2048, 64, 2048, 640, 1.f,
                                      nullptr, nullptr);
        k_deccell<<<64, 512>>>();

        // q = (h* @ WqT + bq) * 0.125
        k_sgemm<<<dim3(8, 1), 256>>>(sp->hstar, 512, sp->WqT, 512,
                                     attn_in_b, nullptr, 0,
                                     sp->q, 512, 64, 512, 512, 0.125f,
                                     nullptr, nullptr);
        k_attn<<<dim3(NHH, BB), 64>>>();

        // y = h* + ctx @ WoutT + b_out
        k_sgemm<<<dim3(8, 1), 256>>>(sp->ctx, 512, sp->WoutT, 512,
                                     attn_out_b, sp->hstar, 512,
                                     sp->y, 512, 64, 512, 512, 1.f,
                                     nullptr, nullptr);
        k_ln<<<64, 512>>>(ln_g, ln_b);

        // logits[:,t,:] = h @ projT + proj_b  (+ per-block argmax partials)
        k_sgemm<<<dim3(NPROJ, 1), 256>>>(sp->z + 128, 640, sp->projT, VV,
                                         proj_b, nullptr, 0,
                                         out + (size_t)t*VV, (size_t)TT*VV > 0 ? TT*VV : TT*VV,
                                         64, VV, 512, 1.f,
                                         sp->pmax, sp->pidx);

        // argmax -> greedy embedding feedback into z[:,0:128]
        k_feedback<<<64, 128>>>(tok_emb);
    }
    (void)in_sizes; (void)n_in; (void)out_size;
}

// round 6
// speedup vs baseline: 1.3043x; 1.3043x over previous
#include <cuda_runtime.h>
#include <cuda_bf16.h>
#include <math.h>

// Problem dims (fixed)
#define BB    64      // batch
#define LL    64      // encoder seq len
#define VV    32000   // vocab
#define TT    32      // decoder steps
#define DEMB  128
#define DENC  256
#define DDEC  512
#define NHH   8
#define HDD   64
#define NPROJ 500     // 32000/64 proj tiles
#define KSPLIT 4

struct Scratch {
    float x[LL*BB*DEMB];          // [L,B,128] token embeddings
    float Xpre[LL*BB*2048];       // x @ [WihT_f | WihT_b]
    float WihT[DEMB*2048];        // [128, 2048]
    float WhhT[DENC*2048];        // [256, 2048]
    float WdecT[640*2048];        // [640, 2048] concat(WihT_dec, WhhT_dec)
    float WqT[512*512];
    float WkvT[512*1024];
    float WoutT[512*512];
    float transferT[512*512];
    float projT[512*VV];          // [512, 32000]
    float mem[LL*BB*512];         // encoder memory [L,B,512]
    float kv[LL*BB*1024];         // k (0..511), v (512..1023)
    float hf[2][BB*DENC];
    float hb[2][BB*DENC];
    float cf[BB*DENC];
    float cb[BB*DENC];
    float z[BB*640];              // [xe(128) | h(512)] decoder input
    float c[BB*512];
    float hstar[BB*512];
    float ctx[BB*512];
    float gpart[KSPLIT*BB*2048];  // K-split partials for gates GEMM
    float qpart[KSPLIT*BB*512];
    float opart[KSPLIT*BB*512];
    float pmax[BB*512];
    int   pidx[BB*512];
};

__device__ Scratch S;

__device__ __forceinline__ float sigf(float x){ return 1.0f/(1.0f + expf(-x)); }

// ---------------------------------------------------------------------------
// init: zero encoder states, seed decoder xe with start_emb
// ---------------------------------------------------------------------------
__global__ void k_init(const float* __restrict__ start_emb){
    int i = blockIdx.x*blockDim.x + threadIdx.x;
    int stride = gridDim.x*blockDim.x;
    for (int idx=i; idx < BB*DENC; idx += stride){
        S.hf[0][idx]=0.f; S.hb[0][idx]=0.f; S.cf[idx]=0.f; S.cb[idx]=0.f;
    }
    for (int idx=i; idx < BB*DEMB; idx += stride)
        S.z[(idx>>7)*640 + (idx&127)] = start_emb[idx&127];
}

// ---------------------------------------------------------------------------
// embed: x[l,b,:] = tok_emb[nx[b,l]]
// ---------------------------------------------------------------------------
__global__ void k_embed(const int* __restrict__ nx, const float* __restrict__ tok_emb){
    int n = blockIdx.x;                 // n = l*B + b
    int e = threadIdx.x;                // 128 threads
    int l = n >> 6, b = n & 63;
    S.x[(size_t)n*DEMB + e] = tok_emb[(size_t)nx[b*LL + l]*DEMB + e];
}

// ---------------------------------------------------------------------------
// generic 32x32 tiled transpose: dst[k*dld + j] = src[(row0+j)*ncols + k]
// ---------------------------------------------------------------------------
__global__ void k_transpose(const float* __restrict__ src, int row0, int nrows,
                            int ncols, float* __restrict__ dst, int dld){
    __shared__ float tile[32][33];
    int j0 = blockIdx.x*32, k0 = blockIdx.y*32;
    int x = threadIdx.x;
    #pragma unroll
    for (int i=0;i<32;i+=8){
        int j = j0 + threadIdx.y + i;
        int k = k0 + x;
        tile[threadIdx.y+i][x] = (j<nrows && k<ncols) ? src[(size_t)(row0+j)*ncols + k] : 0.f;
    }
    __syncthreads();
    #pragma unroll
    for (int i=0;i<32;i+=8){
        int k = k0 + threadIdx.y + i;
        int j = j0 + x;
        if (k<ncols && j<nrows) dst[(size_t)k*dld + j] = tile[x][threadIdx.y+i];
    }
}

// ---------------------------------------------------------------------------
// Pipelined fp32 SGEMM: BM=BN=64, BK=16, 256 threads, 4x4 microtile,
// register prefetch + double-buffered smem (1 sync/tile).
// K-split mode: gridDim.z > 1, each z handles [z*Klen, min(K,(z+1)*Klen)),
//   raw partial written to C + z*zstride (no bias/alpha/resid).
// Full mode (zstride==0): C = alpha*(A@B + bias) + resid, optional per-block
//   row-argmax epilogue (requires gridDim.y==1, M==64).
// ---------------------------------------------------------------------------
__global__ void __launch_bounds__(256, 2) k_sgemm(
    const float* __restrict__ A, int lda,
    const float* __restrict__ B, int ldb,
    const float* __restrict__ bias,
    const float* __restrict__ resid, int ldr,
    float* __restrict__ C, int ldc, long long zstride,
    int K, int Klen, float alpha,
    float* __restrict__ pmax, int* __restrict__ pidx)
{
    __shared__ float As[2][16][68];
    __shared__ float Bs[2][16][64];
    int tid = threadIdx.x;
    int tx = tid & 15, ty = tid >> 4;
    int m0 = blockIdx.y*64, n0 = blockIdx.x*64;
    int kstart = blockIdx.z*Klen;
    int kend   = min(K, kstart + Klen);
    int ntiles = (kend - kstart) >> 4;
    float acc[4][4] = {};
    float aR[4], bR[4];

    // preload tile 0 into regs -> smem[0]
    #pragma unroll
    for (int u=0;u<4;u++){
        int idx = tid + u*256;
        aR[u] = A[(size_t)(m0 + (idx>>4))*lda + kstart + (idx&15)];
        bR[u] = B[(size_t)(kstart + (idx>>6))*ldb + n0 + (idx&63)];
    }
    #pragma unroll
    for (int u=0;u<4;u++){
        int idx = tid + u*256;
        As[0][idx&15][idx>>4] = aR[u];
        Bs[0][idx>>6][idx&63] = bR[u];
    }
    __syncthreads();

    for (int t=0; t<ntiles; t++){
        int cur = t & 1;
        if (t+1 < ntiles){
            int kb = kstart + (t+1)*16;
            #pragma unroll
            for (int u=0;u<4;u++){
                int idx = tid + u*256;
                aR[u] = A[(size_t)(m0 + (idx>>4))*lda + kb + (idx&15)];
                bR[u] = B[(size_t)(kb + (idx>>6))*ldb + n0 + (idx&63)];
            }
        }
        #pragma unroll
        for (int k=0;k<16;k++){
            float4 a4 = *(const float4*)&As[cur][k][ty*4];
            float4 b4 = *(const float4*)&Bs[cur][k][tx*4];
            float av[4] = {a4.x,a4.y,a4.z,a4.w};
            float bv[4] = {b4.x,b4.y,b4.z,b4.w};
            #pragma unroll
            for (int r=0;r<4;r++)
                #pragma unroll
                for (int c=0;c<4;c++)
                    acc[r][c] += av[r]*bv[c];
        }
        if (t+1 < ntiles){
            int nxt = cur ^ 1;
            #pragma unroll
            for (int u=0;u<4;u++){
                int idx = tid + u*256;
                As[nxt][idx&15][idx>>4] = aR[u];
                Bs[nxt][idx>>6][idx&63] = bR[u];
            }
        }
        __syncthreads();
    }

    if (zstride){
        float* Cp = C + (size_t)blockIdx.z*zstride;
        #pragma unroll
        for (int r=0;r<4;r++)
            #pragma unroll
            for (int c=0;c<4;c++)
                Cp[(size_t)(m0+ty*4+r)*ldc + n0+tx*4+c] = acc[r][c];
        return;
    }

    float rowmax[4]; int rowidx[4];
    #pragma unroll
    for (int r=0;r<4;r++){
        int m = m0 + ty*4 + r;
        float bm = -1e30f; int bi = 0;
        #pragma unroll
        for (int c=0;c<4;c++){
            int n = n0 + tx*4 + c;
            float v = acc[r][c];
            if (bias)  v += bias[n];
            v *= alpha;
            if (resid) v += resid[(size_t)m*ldr + n];
            C[(size_t)m*ldc + n] = v;
            if (v > bm){ bm = v; bi = n; }
        }
        rowmax[r] = bm; rowidx[r] = bi;
    }

    if (pmax){
        __shared__ float smx[64][17];
        __shared__ int   smi[64][17];
        #pragma unroll
        for (int r=0;r<4;r++){ smx[ty*4+r][tx] = rowmax[r]; smi[ty*4+r][tx] = rowidx[r]; }
        __syncthreads();
        if (tid < 64){
            float bm = -1e30f; int bi = 0;
            #pragma unroll
            for (int c=0;c<16;c++){
                float v = smx[tid][c];
                if (v > bm){ bm = v; bi = smi[tid][c]; }
            }
            pmax[tid*512 + blockIdx.x] = bm;
            pidx[tid*512 + blockIdx.x] = bi;
        }
    }
}

// ---------------------------------------------------------------------------
// encoder step (both directions): gates = Xpre + h@WhhT + b, LSTM cell.
// Ping-pong h buffers on t parity.
// ---------------------------------------------------------------------------
__global__ void __launch_bounds__(256) k_encstep(int t,
        const float* __restrict__ bias_f, const float* __restrict__ bias_b){
    __shared__ float sh[16][256];
    int tid = threadIdx.x;
    int tx = tid & 31, ty = tid >> 5;        // ty 0..7
    int dir = blockIdx.z;
    int b0 = blockIdx.y * 16;
    int jh = blockIdx.x * 32 + tx;

    const float* hrd = dir ? S.hb[t & 1]     : S.hf[t & 1];
    float*       hwr = dir ? S.hb[(t+1)&1]   : S.hf[(t+1)&1];
    float*       cbuf = dir ? S.cb : S.cf;

    for (int idx = tid; idx < 16*256; idx += 256)
        sh[idx >> 8][idx & 255] = hrd[(b0 + (idx >> 8))*256 + (idx & 255)];
    __syncthreads();

    const float* W = S.WhhT + dir*1024 + jh;
    float a00=0,a01=0,a02=0,a03=0,a10=0,a11=0,a12=0,a13=0;
    #pragma unroll 4
    for (int k=0;k<256;k++){
        const float* wr = W + (size_t)k*2048;
        float w0 = wr[0], w1 = wr[256], w2 = wr[512], w3 = wr[768];
        float h0v = sh[ty][k], h1v = sh[ty+8][k];
        a00 += h0v*w0; a01 += h0v*w1; a02 += h0v*w2; a03 += h0v*w3;
        a10 += h1v*w0; a11 += h1v*w1; a12 += h1v*w2; a13 += h1v*w3;
    }

    int xrow = dir ? (LL - 1 - t) : t;
    const float* bias = dir ? bias_b : bias_f;
    float bi_ = bias[jh], bf_ = bias[256+jh], bg_ = bias[512+jh], bo_ = bias[768+jh];

    #pragma unroll
    for (int rr=0;rr<2;rr++){
        int b = b0 + ty + rr*8;
        const float* xp = S.Xpre + ((size_t)(xrow*BB + b))*2048 + dir*1024;
        float gi = (rr ? a10 : a00) + xp[jh]       + bi_;
        float gf = (rr ? a11 : a01) + xp[256+jh]   + bf_;
        float gg = (rr ? a12 : a02) + xp[512+jh]   + bg_;
        float go = (rr ? a13 : a03) + xp[768+jh]   + bo_;
        float cprev = cbuf[b*256 + jh];
        float cc = sigf(gf)*cprev + sigf(gi)*tanhf(gg);
        float hh = sigf(go)*tanhf(cc);
        cbuf[b*256 + jh] = cc;
        hwr[b*256 + jh]  = hh;
        S.mem[((size_t)xrow*BB + b)*512 + dir*256 + jh] = hh;
    }
}

// ---------------------------------------------------------------------------
// h0 = tanh(concat(hf,hb) @ transferT) -> z[:,128:640];  c0 = style_emb[label]
// ---------------------------------------------------------------------------
__global__ void __launch_bounds__(256) k_h0(const int* __restrict__ label,
                                            const float* __restrict__ style_emb){
    __shared__ float sh[8][512];
    int tid = threadIdx.x, tx = tid & 31, ty = tid >> 5;
    int b0 = blockIdx.y*8;
    int j  = blockIdx.x*32 + tx;
    for (int idx=tid; idx<8*512; idx+=256){
        int r = idx >> 9, c = idx & 511;
        sh[r][c] = (c < 256) ? S.hf[0][(b0+r)*256 + c]
                             : S.hb[0][(b0+r)*256 + c - 256];
    }
    __syncthreads();
    float acc = 0.f;
    #pragma unroll 4
    for (int k=0;k<512;k++) acc += sh[ty][k]*S.transferT[(size_t)k*512 + j];
    int b = b0 + ty;
    S.z[b*640 + 128 + j] = tanhf(acc);
    S.c[b*512 + j] = style_emb[(size_t)label[b]*512 + j];
}

// ---------------------------------------------------------------------------
// reduce gates K-split partials + bias, then LSTM cell (gate order i,f,g,o)
// ---------------------------------------------------------------------------
__global__ void k_cellred(const float* __restrict__ dec_b){
    int b = blockIdx.x, j = threadIdx.x;   // 64 blocks x 512 threads
    float gi = dec_b[j], gf = dec_b[512+j], gg = dec_b[1024+j], go = dec_b[1536+j];
    #pragma unroll
    for (int z=0; z<KSPLIT; z++){
        const float* g = S.gpart + (size_t)z*(BB*2048) + b*2048;
        gi += g[j]; gf += g[512+j]; gg += g[1024+j]; go += g[1536+j];
    }
    float c = sigf(gf)*S.c[b*512+j] + sigf(gi)*tanhf(gg);
    S.c[b*512+j] = c;
    S.hstar[b*512+j] = sigf(go)*tanhf(c);
}

// ---------------------------------------------------------------------------
// single-query multi-head attention, with fused q K-split reduce + bias/scale
// grid (NH, B), 64 threads
// ---------------------------------------------------------------------------
__global__ void k_attn(const float* __restrict__ bq){
    int h = blockIdx.x, b = blockIdx.y;
    int l = threadIdx.x;   // 64
    __shared__ float sq[64], sc[64], red[64];
    {
        int j = h*64 + l;
        float qv = bq[j];
        #pragma unroll
        for (int z=0; z<KSPLIT; z++)
            qv += S.qpart[(size_t)z*(BB*512) + b*512 + j];
        sq[l] = qv * 0.125f;
    }
    __syncthreads();
    const float* kp = S.kv + ((size_t)l*BB + b)*1024 + h*64;
    float s = 0.f;
    #pragma unroll
    for (int d=0;d<64;d++) s += sq[d]*kp[d];
    sc[l] = s; red[l] = s;
    __syncthreads();
    for (int off=32; off; off>>=1){
        if (l < off) red[l] = fmaxf(red[l], red[l+off]);
        __syncthreads();
    }
    float m = red[0];
    __syncthreads();
    float e = expf(s - m);
    sc[l] = e; red[l] = e;
    __syncthreads();
    for (int off=32; off; off>>=1){
        if (l < off) red[l] += red[l+off];
        __syncthreads();
    }
    float inv = 1.f/red[0];
    int d = l;
    float acc = 0.f;
    #pragma unroll 4
    for (int l2=0;l2<64;l2++)
        acc += sc[l2] * S.kv[((size_t)l2*BB + b)*1024 + 512 + h*64 + d];
    S.ctx[b*512 + h*64 + d] = acc * inv;
}

// ---------------------------------------------------------------------------
// reduce attn-out K-split partials + bias + residual(hstar), then LayerNorm
// writes z[:,128:640]
// ---------------------------------------------------------------------------
__global__ void k_outln(const float* __restrict__ ob,
                        const float* __restrict__ lng, const float* __restrict__ lnb){
    int b = blockIdx.x, j = threadIdx.x;   // 64 blocks x 512 threads
    float y = S.hstar[b*512 + j] + ob[j];
    #pragma unroll
    for (int z=0; z<KSPLIT; z++)
        y += S.opart[(size_t)z*(BB*512) + b*512 + j];

    float v1 = y, v2 = y*y;
    #pragma unroll
    for (int off=16; off; off>>=1){
        v1 += __shfl_down_sync(0xffffffffu, v1, off);
        v2 += __shfl_down_sync(0xffffffffu, v2, off);
    }
    __shared__ float s1[16], s2[16];
    __shared__ float mb[2];
    int wid = j >> 5, lane = j & 31;
    if (!lane){ s1[wid] = v1; s2[wid] = v2; }
    __syncthreads();
    if (j == 0){
        float a=0.f, cq=0.f;
        #pragma unroll
        for (int i=0;i<16;i++){ a += s1[i]; cq += s2[i]; }
        float mean = a*(1.f/512.f);
        float var  = cq*(1.f/512.f) - mean*mean;
        mb[0] = mean; mb[1] = rsqrtf(var + 1e-5f);
    }
    __syncthreads();
    S.z[b*640 + 128 + j] = (y - mb[0])*mb[1]*lng[j] + lnb[j];
}

// ---------------------------------------------------------------------------
// argmax reduce over NPROJ partials + embedding feedback -> z[:,0:128]
// ---------------------------------------------------------------------------
__global__ void k_feedback(const float* __restrict__ tok_emb){
    int b = blockIdx.x, t = threadIdx.x;   // 128
    float best = -1e30f; int bi = 0x7fffffff;
    for (int i=t; i<NPROJ; i+=128){
        float v = S.pmax[b*512 + i]; int idx = S.pidx[b*512 + i];
        if (v > best || (v == best && idx < bi)){ best = v; bi = idx; }
    }
    __shared__ float sv[128]; __shared__ int si[128];
    sv[t] = best; si[t] = bi;
    __syncthreads();
    for (int off=64; off; off>>=1){
        if (t < off){
            if (sv[t+off] > sv[t] || (sv[t+off] == sv[t] && si[t+off] < si[t])){
                sv[t] = sv[t+off]; si[t] = si[t+off];
            }
        }
        __syncthreads();
    }
    int tok = si[0];
    S.z[b*640 + t] = tok_emb[(size_t)tok*DEMB + t];
}

// ---------------------------------------------------------------------------
// host launch
// ---------------------------------------------------------------------------
extern "C" void kernel_launch(void* const* d_in, const int* in_sizes, int n_in,
                              void* d_out, int out_size){
    const int*   nx         = (const int*)  d_in[0];
    const int*   label      = (const int*)  d_in[1];
    const float* start_emb  = (const float*)d_in[2];
    const float* tok_emb    = (const float*)d_in[3];
    const float* style_emb  = (const float*)d_in[4];
    const float* enc_Wih_f  = (const float*)d_in[5];
    const float* enc_Whh_f  = (const float*)d_in[6];
    const float* enc_b_f    = (const float*)d_in[7];
    const float* enc_Wih_b  = (const float*)d_in[8];
    const float* enc_Whh_b  = (const float*)d_in[9];
    const float* enc_b_b    = (const float*)d_in[10];
    const float* transfer_W = (const float*)d_in[11];
    const float* dec_Wih    = (const float*)d_in[12];
    const float* dec_Whh    = (const float*)d_in[13];
    const float* dec_b      = (const float*)d_in[14];
    const float* attn_in_w  = (const float*)d_in[15];
    const float* attn_in_b  = (const float*)d_in[16];
    const float* attn_out_w = (const float*)d_in[17];
    const float* attn_out_b = (const float*)d_in[18];
    const float* proj_W     = (const float*)d_in[19];
    const float* proj_b     = (const float*)d_in[20];
    const float* ln_g       = (const float*)d_in[21];
    const float* ln_b       = (const float*)d_in[22];
    float* out = (float*)d_out;

    Scratch* sp;
    cudaGetSymbolAddress((void**)&sp, S);

    dim3 tb(32, 8);

    // ---- setup ----
    k_init<<<64, 256>>>(start_emb);
    k_embed<<<LL*BB, 128>>>(nx, tok_emb);

    // weight transposes
    k_transpose<<<dim3(32,  4),  tb>>>(enc_Wih_f, 0, 1024, 128, sp->WihT,              2048);
    k_transpose<<<dim3(32,  4),  tb>>>(enc_Wih_b, 0, 1024, 128, sp->WihT + 1024,       2048);
    k_transpose<<<dim3(32,  8),  tb>>>(enc_Whh_f, 0, 1024, 256, sp->WhhT,              2048);
    k_transpose<<<dim3(32,  8),  tb>>>(enc_Whh_b, 0, 1024, 256, sp->WhhT + 1024,       2048);
    k_transpose<<<dim3(64,  4),  tb>>>(dec_Wih,   0, 2048, 128, sp->WdecT,             2048);
    k_transpose<<<dim3(64, 16),  tb>>>(dec_Whh,   0, 2048, 512, sp->WdecT + 128*2048,  2048);
    k_transpose<<<dim3(16, 16),  tb>>>(attn_in_w,    0, 512, 512, sp->WqT,              512);
    k_transpose<<<dim3(16, 16),  tb>>>(attn_in_w,  512, 512, 512, sp->WkvT,            1024);
    k_transpose<<<dim3(16, 16),  tb>>>(attn_in_w, 1024, 512, 512, sp->WkvT + 512,      1024);
    k_transpose<<<dim3(16, 16),  tb>>>(attn_out_w,   0, 512, 512, sp->WoutT,            512);
    k_transpose<<<dim3(16, 16),  tb>>>(transfer_W,   0, 512, 512, sp->transferT,        512);
    k_transpose<<<dim3(1000,16), tb>>>(proj_W,       0, VV,  512, sp->projT,            VV);

    // Xpre = x @ [WihT_f | WihT_b]   (M=4096, N=2048, K=128)
    k_sgemm<<<dim3(32, 64, 1), 256>>>(sp->x, 128, sp->WihT, 2048,
                                      nullptr, nullptr, 0,
                                      sp->Xpre, 2048, 0LL, 128, 128, 1.f,
                                      nullptr, nullptr);

    // ---- encoder recurrence (both dirs per launch) ----
    for (int t=0; t<LL; t++)
        k_encstep<<<dim3(8, 4, 2), 256>>>(t, enc_b_f, enc_b_b);

    // h0 / c0
    k_h0<<<dim3(16, 8), 256>>>(label, style_emb);

    // k,v = memory @ WkvT + [bk|bv]   (M=4096, N=1024, K=512)
    k_sgemm<<<dim3(16, 64, 1), 256>>>(sp->mem, 512, sp->WkvT, 1024,
                                      attn_in_b + 512, nullptr, 0,
                                      sp->kv, 1024, 0LL, 512, 512, 1.f,
                                      nullptr, nullptr);

    // ---- decoder ----
    for (int t=0; t<TT; t++){
        // gates partials: z @ WdecT   (M=64, N=2048, K=640, split 4x160)
        k_sgemm<<<dim3(32, 1, KSPLIT), 256>>>(sp->z, 640, sp->WdecT, 2048,
                                              nullptr, nullptr, 0,
                                              sp->gpart, 2048, (long long)BB*2048,
                                              640, 160, 1.f, nullptr, nullptr);
        // reduce + bias + LSTM cell
        k_cellred<<<64, 512>>>(dec_b);

        // q partials: h* @ WqT  (M=64, N=512, K=512, split 4x128)
        k_sgemm<<<dim3(8, 1, KSPLIT), 256>>>(sp->hstar, 512, sp->WqT, 512,
                                             nullptr, nullptr, 0,
                                             sp->qpart, 512, (long long)BB*512,
                                             512, 128, 1.f, nullptr, nullptr);
        // attention (fuses q reduce + bias + scale)
        k_attn<<<dim3(NHH, BB), 64>>>(attn_in_b);

        // out partials: ctx @ WoutT  (M=64, N=512, K=512, split 4x128)
        k_sgemm<<<dim3(8, 1, KSPLIT), 256>>>(sp->ctx, 512, sp->WoutT, 512,
                                             nullptr, nullptr, 0,
                                             sp->opart, 512, (long long)BB*512,
                                             512, 128, 1.f, nullptr, nullptr);
        // reduce + bias + residual + LayerNorm -> z[:,128:640]
        k_outln<<<64, 512>>>(attn_out_b, ln_g, ln_b);

        // logits[:,t,:] = h @ projT + proj_b  (+ per-block argmax partials)
        k_sgemm<<<dim3(NPROJ, 1, 1), 256>>>(sp->z + 128, 640, sp->projT, VV,
                                            proj_b, nullptr, 0,
                                            out + (size_t)t*VV, TT*VV, 0LL,
                                            512, 512, 1.f,
                                            sp->pmax, sp->pidx);

        // argmax -> greedy embedding feedback into z[:,0:128]
        k_feedback<<<64, 128>>>(tok_emb);
    }
    (void)in_sizes; (void)n_in; (void)out_size;
}

// round 7
// speedup vs baseline: 1.6835x; 1.2907x over previous
#include <cuda_runtime.h>
#include <cuda_bf16.h>
#include <math.h>
#include <mma.h>

using namespace nvcuda;

// Problem dims (fixed)
#define BB    64      // batch
#define LL    64      // encoder seq len
#define VV    32000   // vocab
#define TT    32      // decoder steps
#define DEMB  128
#define DENC  256
#define DDEC  512
#define NHH   8
#define HDD   64
#define NPROJ 250     // 32000/128 proj tiles
#define KSPLIT 4

struct __align__(256) Scratch {
    float x[LL*BB*DEMB];          // [L,B,128] token embeddings
    float Xpre[LL*BB*2048];       // x @ [WihT_f | WihT_b]
    float WihT[DEMB*2048];        // [128, 2048]
    float WhhT[DENC*2048];        // [256, 2048]
    float WdecT[640*2048];        // [640, 2048] concat(WihT_dec, WhhT_dec)
    float WqT[512*512];
    float WkvT[512*1024];
    float WoutT[512*512];
    float transferT[512*512];
    float mem[LL*BB*512];         // encoder memory [L,B,512]
    float kv[LL*BB*1024];         // k (0..511), v (512..1023)
    float hf[2][BB*DENC];
    float hb[2][BB*DENC];
    float cf[BB*DENC];
    float cb[BB*DENC];
    float z[BB*640];              // [xe(128) | h(512)] decoder input
    float c[BB*512];
    float hstar[BB*512];
    float ctx[BB*512];
    float gpart[KSPLIT*BB*2048];  // K-split partials for gates GEMM
    float qpart[KSPLIT*BB*512];
    float opart[KSPLIT*BB*512];
    float pmax[BB*512];
    int   pidx[BB*512];
    __nv_bfloat16 Whi[(size_t)VV*512];   // proj_W split, original [V,512] layout
    __nv_bfloat16 Wlo[(size_t)VV*512];
    __nv_bfloat16 hsphi[BB*512];         // h (post-LN) split
    __nv_bfloat16 hsplo[BB*512];
};

__device__ Scratch S;

__device__ __forceinline__ float sigf(float x){ return 1.0f/(1.0f + expf(-x)); }

// ---------------------------------------------------------------------------
// init: zero encoder states, seed decoder xe with start_emb
// ---------------------------------------------------------------------------
__global__ void k_init(const float* __restrict__ start_emb){
    int i = blockIdx.x*blockDim.x + threadIdx.x;
    int stride = gridDim.x*blockDim.x;
    for (int idx=i; idx < BB*DENC; idx += stride){
        S.hf[0][idx]=0.f; S.hb[0][idx]=0.f; S.cf[idx]=0.f; S.cb[idx]=0.f;
    }
    for (int idx=i; idx < BB*DEMB; idx += stride)
        S.z[(idx>>7)*640 + (idx&127)] = start_emb[idx&127];
}

// ---------------------------------------------------------------------------
// embed: x[l,b,:] = tok_emb[nx[b,l]]
// ---------------------------------------------------------------------------
__global__ void k_embed(const int* __restrict__ nx, const float* __restrict__ tok_emb){
    int n = blockIdx.x;                 // n = l*B + b
    int e = threadIdx.x;                // 128 threads
    int l = n >> 6, b = n & 63;
    S.x[(size_t)n*DEMB + e] = tok_emb[(size_t)nx[b*LL + l]*DEMB + e];
}

// ---------------------------------------------------------------------------
// split proj_W into bf16 hi + bf16 residual (keeps [V,512] layout)
// ---------------------------------------------------------------------------
__global__ void k_wsplit(const float* __restrict__ W){
    size_t n = (size_t)VV*512;
    for (size_t i = (size_t)blockIdx.x*blockDim.x + threadIdx.x; i < n;
         i += (size_t)gridDim.x*blockDim.x){
        float w = W[i];
        __nv_bfloat16 hi = __float2bfloat16(w);
        float lo = w - __bfloat162float(hi);
        S.Whi[i] = hi;
        S.Wlo[i] = __float2bfloat16(lo);
    }
}

// ---------------------------------------------------------------------------
// generic 32x32 tiled transpose: dst[k*dld + j] = src[(row0+j)*ncols + k]
// ---------------------------------------------------------------------------
__global__ void k_transpose(const float* __restrict__ src, int row0, int nrows,
                            int ncols, float* __restrict__ dst, int dld){
    __shared__ float tile[32][33];
    int j0 = blockIdx.x*32, k0 = blockIdx.y*32;
    int x = threadIdx.x;
    #pragma unroll
    for (int i=0;i<32;i+=8){
        int j = j0 + threadIdx.y + i;
        int k = k0 + x;
        tile[threadIdx.y+i][x] = (j<nrows && k<ncols) ? src[(size_t)(row0+j)*ncols + k] : 0.f;
    }
    __syncthreads();
    #pragma unroll
    for (int i=0;i<32;i+=8){
        int k = k0 + threadIdx.y + i;
        int j = j0 + x;
        if (k<ncols && j<nrows) dst[(size_t)k*dld + j] = tile[x][threadIdx.y+i];
    }
}

// ---------------------------------------------------------------------------
// Pipelined fp32 SGEMM (unchanged from R5): BM=BN=64, BK=16, 256 thr, 4x4.
// ---------------------------------------------------------------------------
__global__ void __launch_bounds__(256, 2) k_sgemm(
    const float* __restrict__ A, int lda,
    const float* __restrict__ B, int ldb,
    const float* __restrict__ bias,
    const float* __restrict__ resid, int ldr,
    float* __restrict__ C, int ldc, long long zstride,
    int K, int Klen, float alpha)
{
    __shared__ float As[2][16][68];
    __shared__ float Bs[2][16][64];
    int tid = threadIdx.x;
    int tx = tid & 15, ty = tid >> 4;
    int m0 = blockIdx.y*64, n0 = blockIdx.x*64;
    int kstart = blockIdx.z*Klen;
    int kend   = min(K, kstart + Klen);
    int ntiles = (kend - kstart) >> 4;
    float acc[4][4] = {};
    float aR[4], bR[4];

    #pragma unroll
    for (int u=0;u<4;u++){
        int idx = tid + u*256;
        aR[u] = A[(size_t)(m0 + (idx>>4))*lda + kstart + (idx&15)];
        bR[u] = B[(size_t)(kstart + (idx>>6))*ldb + n0 + (idx&63)];
    }
    #pragma unroll
    for (int u=0;u<4;u++){
        int idx = tid + u*256;
        As[0][idx&15][idx>>4] = aR[u];
        Bs[0][idx>>6][idx&63] = bR[u];
    }
    __syncthreads();

    for (int t=0; t<ntiles; t++){
        int cur = t & 1;
        if (t+1 < ntiles){
            int kb = kstart + (t+1)*16;
            #pragma unroll
            for (int u=0;u<4;u++){
                int idx = tid + u*256;
                aR[u] = A[(size_t)(m0 + (idx>>4))*lda + kb + (idx&15)];
                bR[u] = B[(size_t)(kb + (idx>>6))*ldb + n0 + (idx&63)];
            }
        }
        #pragma unroll
        for (int k=0;k<16;k++){
            float4 a4 = *(const float4*)&As[cur][k][ty*4];
            float4 b4 = *(const float4*)&Bs[cur][k][tx*4];
            float av[4] = {a4.x,a4.y,a4.z,a4.w};
            float bv[4] = {b4.x,b4.y,b4.z,b4.w};
            #pragma unroll
            for (int r=0;r<4;r++)
                #pragma unroll
                for (int c=0;c<4;c++)
                    acc[r][c] += av[r]*bv[c];
        }
        if (t+1 < ntiles){
            int nxt = cur ^ 1;
            #pragma unroll
            for (int u=0;u<4;u++){
                int idx = tid + u*256;
                As[nxt][idx&15][idx>>4] = aR[u];
                Bs[nxt][idx>>6][idx&63] = bR[u];
            }
        }
        __syncthreads();
    }

    if (zstride){
        float* Cp = C + (size_t)blockIdx.z*zstride;
        #pragma unroll
        for (int r=0;r<4;r++)
            #pragma unroll
            for (int c=0;c<4;c++)
                Cp[(size_t)(m0+ty*4+r)*ldc + n0+tx*4+c] = acc[r][c];
        return;
    }

    #pragma unroll
    for (int r=0;r<4;r++){
        int m = m0 + ty*4 + r;
        #pragma unroll
        for (int c=0;c<4;c++){
            int n = n0 + tx*4 + c;
            float v = acc[r][c];
            if (bias)  v += bias[n];
            v *= alpha;
            if (resid) v += resid[(size_t)m*ldr + n];
            C[(size_t)m*ldc + n] = v;
        }
    }
}

// ---------------------------------------------------------------------------
// Tensor-core proj GEMM: C[64,32000] = (Ahi+Alo) @ (Whi+Wlo)^T + bias
// 3-product bf16 split (hi*hi + hi*lo + lo*hi), fp32 accumulate.
// B original layout [V,512] = col-major K x N with ld=512 -> no transpose.
// BM=64, BN=128, BK=32, 256 threads (8 warps: 4 m-tiles x 2 n-halves).
// cp.async double-buffered B staging; C staged to smem (aliases B buffers)
// for bias + per-row argmax epilogue.
// ---------------------------------------------------------------------------
__global__ void __launch_bounds__(256, 2) k_projmma(
    const __nv_bfloat16* __restrict__ Ahi, const __nv_bfloat16* __restrict__ Alo,
    const __nv_bfloat16* __restrict__ Bhi, const __nv_bfloat16* __restrict__ Blo,
    const float* __restrict__ bias,
    float* __restrict__ Cout, long long ldc,
    float* __restrict__ pmax, int* __restrict__ pidx)
{
    __shared__ __align__(16) char sraw[40960];
    typedef __nv_bfloat16 (*BsT)[2][128][40];   // [buf][hi/lo][n][k(+pad)]
    BsT Bs = (BsT)sraw;
    float (*Cs)[132] = (float(*)[132])sraw;

    int tid  = threadIdx.x;
    int warp = tid >> 5;
    int mw   = warp & 3;      // m tile (16 rows)
    int nw   = warp >> 2;     // n half (64 cols)
    int n0   = blockIdx.x * 128;

    wmma::fragment<wmma::accumulator,16,16,16,float> acc[4];
    #pragma unroll
    for (int j=0;j<4;j++) wmma::fill_fragment(acc[j], 0.0f);

    // issue cp.async copy of 32-wide k-chunk kc into buffer buf
    auto issue = [&](int buf, int kc){
        int k0 = kc*32;
        #pragma unroll
        for (int u=0;u<4;u++){
            int c = tid + u*256;          // 0..1023 chunks of 16B
            int hilo = c >> 9;
            int r    = (c >> 2) & 127;
            int v    = c & 3;
            const __nv_bfloat16* src = (hilo ? Blo : Bhi)
                + (size_t)(n0 + r)*512 + k0 + v*8;
            unsigned dst = (unsigned)__cvta_generic_to_shared(&Bs[buf][hilo][r][v*8]);
            asm volatile("cp.async.cg.shared.global [%0], [%1], 16;" :: "r"(dst), "l"(src));
        }
        asm volatile("cp.async.commit_group;");
    };

    issue(0, 0);
    for (int t=0; t<16; t++){
        int cur = t & 1;
        if (t < 15){
            issue(cur^1, t+1);
            asm volatile("cp.async.wait_group 1;");
        } else {
            asm volatile("cp.async.wait_group 0;");
        }
        __syncthreads();
        #pragma unroll
        for (int ks=0; ks<2; ks++){
            int k16 = t*32 + ks*16;
            wmma::fragment<wmma::matrix_a,16,16,16,__nv_bfloat16,wmma::row_major> ahi, alo;
            wmma::load_matrix_sync(ahi, Ahi + (size_t)(mw*16)*512 + k16, 512);
            wmma::load_matrix_sync(alo, Alo + (size_t)(mw*16)*512 + k16, 512);
            #pragma unroll
            for (int j=0;j<4;j++){
                wmma::fragment<wmma::matrix_b,16,16,16,__nv_bfloat16,wmma::col_major> bhi, blo;
                int nl = nw*64 + j*16;
                wmma::load_matrix_sync(bhi, &Bs[cur][0][nl][ks*16], 40);
                wmma::load_matrix_sync(blo, &Bs[cur][1][nl][ks*16], 40);
                wmma::mma_sync(acc[j], ahi, bhi, acc[j]);
                wmma::mma_sync(acc[j], ahi, blo, acc[j]);
                wmma::mma_sync(acc[j], alo, bhi, acc[j]);
            }
        }
        __syncthreads();   // all warps done with buf 'cur' before it's refilled
    }

    // stage C to smem (aliases Bs; loop above ended with syncthreads)
    #pragma unroll
    for (int j=0;j<4;j++)
        wmma::store_matrix_sync(&Cs[mw*16][nw*64 + j*16], acc[j], 132, wmma::mem_row_major);
    __syncthreads();

    // epilogue: bias add, global write, per-row argmax partial
    int r  = tid >> 2;        // 0..63
    int c0 = tid & 3;
    float best = -1e30f; int bi = 0;
    #pragma unroll
    for (int i=0;i<32;i++){
        int c = c0 + i*4;
        float v = Cs[r][c] + bias[n0 + c];
        Cout[(size_t)r*ldc + n0 + c] = v;
        if (v > best){ best = v; bi = n0 + c; }
    }
    #pragma unroll
    for (int off=1; off<4; off<<=1){
        float v2 = __shfl_xor_sync(0xffffffffu, best, off);
        int   i2 = __shfl_xor_sync(0xffffffffu, bi,   off);
        if (v2 > best || (v2 == best && i2 < bi)){ best = v2; bi = i2; }
    }
    if (c0 == 0){
        pmax[r*512 + blockIdx.x] = best;
        pidx[r*512 + blockIdx.x] = bi;
    }
}

// ---------------------------------------------------------------------------
// encoder step (both directions): gates = Xpre + h@WhhT + b, LSTM cell.
// ---------------------------------------------------------------------------
__global__ void __launch_bounds__(256) k_encstep(int t,
        const float* __restrict__ bias_f, const float* __restrict__ bias_b){
    __shared__ float sh[16][256];
    int tid = threadIdx.x;
    int tx = tid & 31, ty = tid >> 5;
    int dir = blockIdx.z;
    int b0 = blockIdx.y * 16;
    int jh = blockIdx.x * 32 + tx;

    const float* hrd = dir ? S.hb[t & 1]     : S.hf[t & 1];
    float*       hwr = dir ? S.hb[(t+1)&1]   : S.hf[(t+1)&1];
    float*       cbuf = dir ? S.cb : S.cf;

    for (int idx = tid; idx < 16*256; idx += 256)
        sh[idx >> 8][idx & 255] = hrd[(b0 + (idx >> 8))*256 + (idx & 255)];
    __syncthreads();

    const float* W = S.WhhT + dir*1024 + jh;
    float a00=0,a01=0,a02=0,a03=0,a10=0,a11=0,a12=0,a13=0;
    #pragma unroll 4
    for (int k=0;k<256;k++){
        const float* wr = W + (size_t)k*2048;
        float w0 = wr[0], w1 = wr[256], w2 = wr[512], w3 = wr[768];
        float h0v = sh[ty][k], h1v = sh[ty+8][k];
        a00 += h0v*w0; a01 += h0v*w1; a02 += h0v*w2; a03 += h0v*w3;
        a10 += h1v*w0; a11 += h1v*w1; a12 += h1v*w2; a13 += h1v*w3;
    }

    int xrow = dir ? (LL - 1 - t) : t;
    const float* bias = dir ? bias_b : bias_f;
    float bi_ = bias[jh], bf_ = bias[256+jh], bg_ = bias[512+jh], bo_ = bias[768+jh];

    #pragma unroll
    for (int rr=0;rr<2;rr++){
        int b = b0 + ty + rr*8;
        const float* xp = S.Xpre + ((size_t)(xrow*BB + b))*2048 + dir*1024;
        float gi = (rr ? a10 : a00) + xp[jh]       + bi_;
        float gf = (rr ? a11 : a01) + xp[256+jh]   + bf_;
        float gg = (rr ? a12 : a02) + xp[512+jh]   + bg_;
        float go = (rr ? a13 : a03) + xp[768+jh]   + bo_;
        float cprev = cbuf[b*256 + jh];
        float cc = sigf(gf)*cprev + sigf(gi)*tanhf(gg);
        float hh = sigf(go)*tanhf(cc);
        cbuf[b*256 + jh] = cc;
        hwr[b*256 + jh]  = hh;
        S.mem[((size_t)xrow*BB + b)*512 + dir*256 + jh] = hh;
    }
}

// ---------------------------------------------------------------------------
// h0 = tanh(concat(hf,hb) @ transferT) -> z[:,128:640] (+ bf16 split);
// c0 = style_emb[label]
// ---------------------------------------------------------------------------
__global__ void __launch_bounds__(256) k_h0(const int* __restrict__ label,
                                            const float* __restrict__ style_emb){
    __shared__ float sh[8][512];
    int tid = threadIdx.x, tx = tid & 31, ty = tid >> 5;
    int b0 = blockIdx.y*8;
    int j  = blockIdx.x*32 + tx;
    for (int idx=tid; idx<8*512; idx+=256){
        int r = idx >> 9, c = idx & 511;
        sh[r][c] = (c < 256) ? S.hf[0][(b0+r)*256 + c]
                             : S.hb[0][(b0+r)*256 + c - 256];
    }
    __syncthreads();
    float acc = 0.f;
    #pragma unroll 4
    for (int k=0;k<512;k++) acc += sh[ty][k]*S.transferT[(size_t)k*512 + j];
    int b = b0 + ty;
    float hv = tanhf(acc);
    S.z[b*640 + 128 + j] = hv;
    __nv_bfloat16 hi = __float2bfloat16(hv);
    S.hsphi[b*512 + j] = hi;
    S.hsplo[b*512 + j] = __float2bfloat16(hv - __bfloat162float(hi));
    S.c[b*512 + j] = style_emb[(size_t)label[b]*512 + j];
}

// ---------------------------------------------------------------------------
// reduce gates K-split partials + bias, then LSTM cell (i,f,g,o)
// ---------------------------------------------------------------------------
__global__ void k_cellred(const float* __restrict__ dec_b){
    int b = blockIdx.x, j = threadIdx.x;   // 64 blocks x 512 threads
    float gi = dec_b[j], gf = dec_b[512+j], gg = dec_b[1024+j], go = dec_b[1536+j];
    #pragma unroll
    for (int z=0; z<KSPLIT; z++){
        const float* g = S.gpart + (size_t)z*(BB*2048) + b*2048;
        gi += g[j]; gf += g[512+j]; gg += g[1024+j]; go += g[1536+j];
    }
    float c = sigf(gf)*S.c[b*512+j] + sigf(gi)*tanhf(gg);
    S.c[b*512+j] = c;
    S.hstar[b*512+j] = sigf(go)*tanhf(c);
}

// ---------------------------------------------------------------------------
// attention with fused q K-split reduce + bias/scale. grid (NH, B), 64 thr.
// ---------------------------------------------------------------------------
__global__ void k_attn(const float* __restrict__ bq){
    int h = blockIdx.x, b = blockIdx.y;
    int l = threadIdx.x;   // 64
    __shared__ float sq[64], sc[64], red[64];
    {
        int j = h*64 + l;
        float qv = bq[j];
        #pragma unroll
        for (int z=0; z<KSPLIT; z++)
            qv += S.qpart[(size_t)z*(BB*512) + b*512 + j];
        sq[l] = qv * 0.125f;
    }
    __syncthreads();
    const float* kp = S.kv + ((size_t)l*BB + b)*1024 + h*64;
    float s = 0.f;
    #pragma unroll
    for (int d=0;d<64;d++) s += sq[d]*kp[d];
    sc[l] = s; red[l] = s;
    __syncthreads();
    for (int off=32; off; off>>=1){
        if (l < off) red[l] = fmaxf(red[l], red[l+off]);
        __syncthreads();
    }
    float m = red[0];
    __syncthreads();
    float e = expf(s - m);
    sc[l] = e; red[l] = e;
    __syncthreads();
    for (int off=32; off; off>>=1){
        if (l < off) red[l] += red[l+off];
        __syncthreads();
    }
    float inv = 1.f/red[0];
    int d = l;
    float acc = 0.f;
    #pragma unroll 4
    for (int l2=0;l2<64;l2++)
        acc += sc[l2] * S.kv[((size_t)l2*BB + b)*1024 + 512 + h*64 + d];
    S.ctx[b*512 + h*64 + d] = acc * inv;
}

// ---------------------------------------------------------------------------
// reduce attn-out K-split partials + bias + residual, LayerNorm,
// write z[:,128:640] and bf16 hi/lo split for the proj GEMM.
// ---------------------------------------------------------------------------
__global__ void k_outln(const float* __restrict__ ob,
                        const float* __restrict__ lng, const float* __restrict__ lnb){
    int b = blockIdx.x, j = threadIdx.x;   // 64 blocks x 512 threads
    float y = S.hstar[b*512 + j] + ob[j];
    #pragma unroll
    for (int z=0; z<KSPLIT; z++)
        y += S.opart[(size_t)z*(BB*512) + b*512 + j];

    float v1 = y, v2 = y*y;
    #pragma unroll
    for (int off=16; off; off>>=1){
        v1 += __shfl_down_sync(0xffffffffu, v1, off);
        v2 += __shfl_down_sync(0xffffffffu, v2, off);
    }
    __shared__ float s1[16], s2[16];
    __shared__ float mb[2];
    int wid = j >> 5, lane = j & 31;
    if (!lane){ s1[wid] = v1; s2[wid] = v2; }
    __syncthreads();
    if (j == 0){
        float a=0.f, cq=0.f;
        #pragma unroll
        for (int i=0;i<16;i++){ a += s1[i]; cq += s2[i]; }
        float mean = a*(1.f/512.f);
        float var  = cq*(1.f/512.f) - mean*mean;
        mb[0] = mean; mb[1] = rsqrtf(var + 1e-5f);
    }
    __syncthreads();
    float hv = (y - mb[0])*mb[1]*lng[j] + lnb[j];
    S.z[b*640 + 128 + j] = hv;
    __nv_bfloat16 hi = __float2bfloat16(hv);
    S.hsphi[b*512 + j] = hi;
    S.hsplo[b*512 + j] = __float2bfloat16(hv - __bfloat162float(hi));
}

// ---------------------------------------------------------------------------
// argmax reduce over NPROJ partials + embedding feedback -> z[:,0:128]
// ---------------------------------------------------------------------------
__global__ void k_feedback(const float* __restrict__ tok_emb){
    int b = blockIdx.x, t = threadIdx.x;   // 128
    float best = -1e30f; int bi = 0x7fffffff;
    for (int i=t; i<NPROJ; i+=128){
        float v = S.pmax[b*512 + i]; int idx = S.pidx[b*512 + i];
        if (v > best || (v == best && idx < bi)){ best = v; bi = idx; }
    }
    __shared__ float sv[128]; __shared__ int si[128];
    sv[t] = best; si[t] = bi;
    __syncthreads();
    for (int off=64; off; off>>=1){
        if (t < off){
            if (sv[t+off] > sv[t] || (sv[t+off] == sv[t] && si[t+off] < si[t])){
                sv[t] = sv[t+off]; si[t] = si[t+off];
            }
        }
        __syncthreads();
    }
    int tok = si[0];
    S.z[b*640 + t] = tok_emb[(size_t)tok*DEMB + t];
}

// ---------------------------------------------------------------------------
// host launch
// ---------------------------------------------------------------------------
extern "C" void kernel_launch(void* const* d_in, const int* in_sizes, int n_in,
                              void* d_out, int out_size){
    const int*   nx         = (const int*)  d_in[0];
    const int*   label      = (const int*)  d_in[1];
    const float* start_emb  = (const float*)d_in[2];
    const float* tok_emb    = (const float*)d_in[3];
    const float* style_emb  = (const float*)d_in[4];
    const float* enc_Wih_f  = (const float*)d_in[5];
    const float* enc_Whh_f  = (const float*)d_in[6];
    const float* enc_b_f    = (const float*)d_in[7];
    const float* enc_Wih_b  = (const float*)d_in[8];
    const float* enc_Whh_b  = (const float*)d_in[9];
    const float* enc_b_b    = (const float*)d_in[10];
    const float* transfer_W = (const float*)d_in[11];
    const float* dec_Wih    = (const float*)d_in[12];
    const float* dec_Whh    = (const float*)d_in[13];
    const float* dec_b      = (const float*)d_in[14];
    const float* attn_in_w  = (const float*)d_in[15];
    const float* attn_in_b  = (const float*)d_in[16];
    const float* attn_out_w = (const float*)d_in[17];
    const float* attn_out_b = (const float*)d_in[18];
    const float* proj_W     = (const float*)d_in[19];
    const float* proj_b     = (const float*)d_in[20];
    const float* ln_g       = (const float*)d_in[21];
    const float* ln_b       = (const float*)d_in[22];
    float* out = (float*)d_out;

    Scratch* sp;
    cudaGetSymbolAddress((void**)&sp, S);

    dim3 tb(32, 8);

    // ---- setup ----
    k_init<<<64, 256>>>(start_emb);
    k_embed<<<LL*BB, 128>>>(nx, tok_emb);
    k_wsplit<<<4096, 256>>>(proj_W);

    // weight transposes (proj transpose removed; bf16 split replaces it)
    k_transpose<<<dim3(32,  4),  tb>>>(enc_Wih_f, 0, 1024, 128, sp->WihT,              2048);
    k_transpose<<<dim3(32,  4),  tb>>>(enc_Wih_b, 0, 1024, 128, sp->WihT + 1024,       2048);
    k_transpose<<<dim3(32,  8),  tb>>>(enc_Whh_f, 0, 1024, 256, sp->WhhT,              2048);
    k_transpose<<<dim3(32,  8),  tb>>>(enc_Whh_b, 0, 1024, 256, sp->WhhT + 1024,       2048);
    k_transpose<<<dim3(64,  4),  tb>>>(dec_Wih,   0, 2048, 128, sp->WdecT,             2048);
    k_transpose<<<dim3(64, 16),  tb>>>(dec_Whh,   0, 2048, 512, sp->WdecT + 128*2048,  2048);
    k_transpose<<<dim3(16, 16),  tb>>>(attn_in_w,    0, 512, 512, sp->WqT,              512);
    k_transpose<<<dim3(16, 16),  tb>>>(attn_in_w,  512, 512, 512, sp->WkvT,            1024);
    k_transpose<<<dim3(16, 16),  tb>>>(attn_in_w, 1024, 512, 512, sp->WkvT + 512,      1024);
    k_transpose<<<dim3(16, 16),  tb>>>(attn_out_w,   0, 512, 512, sp->WoutT,            512);
    k_transpose<<<dim3(16, 16),  tb>>>(transfer_W,   0, 512, 512, sp->transferT,        512);

    // Xpre = x @ [WihT_f | WihT_b]   (M=4096, N=2048, K=128)
    k_sgemm<<<dim3(32, 64, 1), 256>>>(sp->x, 128, sp->WihT, 2048,
                                      nullptr, nullptr, 0,
                                      sp->Xpre, 2048, 0LL, 128, 128, 1.f);

    // ---- encoder recurrence (both dirs per launch) ----
    for (int t=0; t<LL; t++)
        k_encstep<<<dim3(8, 4, 2), 256>>>(t, enc_b_f, enc_b_b);

    // h0 / c0
    k_h0<<<dim3(16, 8), 256>>>(label, style_emb);

    // k,v = memory @ WkvT + [bk|bv]   (M=4096, N=1024, K=512)
    k_sgemm<<<dim3(16, 64, 1), 256>>>(sp->mem, 512, sp->WkvT, 1024,
                                      attn_in_b + 512, nullptr, 0,
                                      sp->kv, 1024, 0LL, 512, 512, 1.f);

    // ---- decoder ----
    for (int t=0; t<TT; t++){
        // gates partials: z @ WdecT   (M=64, N=2048, K=640, split 4x160)
        k_sgemm<<<dim3(32, 1, KSPLIT), 256>>>(sp->z, 640, sp->WdecT, 2048,
                                              nullptr, nullptr, 0,
                                              sp->gpart, 2048, (long long)BB*2048,
                                              640, 160, 1.f);
        k_cellred<<<64, 512>>>(dec_b);

        // q partials: h* @ WqT  (M=64, N=512, K=512, split 4x128)
        k_sgemm<<<dim3(8, 1, KSPLIT), 256>>>(sp->hstar, 512, sp->WqT, 512,
                                             nullptr, nullptr, 0,
                                             sp->qpart, 512, (long long)BB*512,
                                             512, 128, 1.f);
        k_attn<<<dim3(NHH, BB), 64>>>(attn_in_b);

        // out partials: ctx @ WoutT  (M=64, N=512, K=512, split 4x128)
        k_sgemm<<<dim3(8, 1, KSPLIT), 256>>>(sp->ctx, 512, sp->WoutT, 512,
                                             nullptr, nullptr, 0,
                                             sp->opart, 512, (long long)BB*512,
                                             512, 128, 1.f);
        k_outln<<<64, 512>>>(attn_out_b, ln_g, ln_b);

        // logits[:,t,:] = h @ proj_W^T + proj_b  (tensor-core split-bf16)
        k_projmma<<<NPROJ, 256>>>(sp->hsphi, sp->hsplo, sp->Whi, sp->Wlo,
                                  proj_b, out + (size_t)t*VV, (long long)TT*VV,
                                  sp->pmax, sp->pidx);

        k_feedback<<<64, 128>>>(tok_emb);
    }
    (void)in_sizes; (void)n_in; (void)out_size;
}